// round 3
// baseline (speedup 1.0000x reference)
#include <cuda_runtime.h>
#include <math.h>

#define S       128
#define BSZ     2
#define MD      256
#define NPOS    (BSZ * S * S)      /* 32768 */
#define QKVD    768
#define HD      32
#define NH      8
#define ATT_SCALE 0.17677669529663687f   /* 32^-0.5 */
#define MBIAS   (-1.0e9f)

/* ---- scratch (static device globals: allocation-free) ---- */
__device__ float g_xhat[NPOS * MD];      /* 33.5 MB */
__device__ float g_qkv [NPOS * QKVD];    /* 100 MB  */
__device__ float g_att [NPOS * MD];      /* 33.5 MB */

/* inv_freq[j] = 10000^(-j/8) */
__constant__ float c_invf[8] = {
    1.0f, 0.31622776601683794f, 0.1f, 0.031622776601683794f,
    0.01f, 0.0031622776601683794f, 0.001f, 0.00031622776601683794f
};

/* ==================== LayerNorm: one warp per row ==================== */
__global__ void __launch_bounds__(256) ln_kernel(const float* __restrict__ x,
                                                 const float* __restrict__ gamma,
                                                 const float* __restrict__ beta)
{
    int row  = blockIdx.x * 8 + (threadIdx.x >> 5);
    int lane = threadIdx.x & 31;
    const float* xr = x + (size_t)row * MD;

    float4 a = *(const float4*)(xr + lane * 4);
    float4 b = *(const float4*)(xr + 128 + lane * 4);

    float s  = a.x + a.y + a.z + a.w + b.x + b.y + b.z + b.w;
    float ss = a.x*a.x + a.y*a.y + a.z*a.z + a.w*a.w
             + b.x*b.x + b.y*b.y + b.z*b.z + b.w*b.w;
#pragma unroll
    for (int o = 16; o > 0; o >>= 1) {
        s  += __shfl_xor_sync(0xffffffffu, s,  o);
        ss += __shfl_xor_sync(0xffffffffu, ss, o);
    }
    float mu   = s  * (1.0f / 256.0f);
    float var  = ss * (1.0f / 256.0f) - mu * mu;
    float rstd = rsqrtf(var + 1e-5f);

    float4 g0 = *(const float4*)(gamma + lane * 4);
    float4 g1 = *(const float4*)(gamma + 128 + lane * 4);
    float4 b0 = *(const float4*)(beta  + lane * 4);
    float4 b1 = *(const float4*)(beta  + 128 + lane * 4);

    float4 r0, r1;
    r0.x = (a.x - mu) * rstd * g0.x + b0.x;
    r0.y = (a.y - mu) * rstd * g0.y + b0.y;
    r0.z = (a.z - mu) * rstd * g0.z + b0.z;
    r0.w = (a.w - mu) * rstd * g0.w + b0.w;
    r1.x = (b.x - mu) * rstd * g1.x + b1.x;
    r1.y = (b.y - mu) * rstd * g1.y + b1.y;
    r1.z = (b.z - mu) * rstd * g1.z + b1.z;
    r1.w = (b.w - mu) * rstd * g1.w + b1.w;

    float* orow = g_xhat + (size_t)row * MD;
    *(float4*)(orow + lane * 4)       = r0;
    *(float4*)(orow + 128 + lane * 4) = r1;
}

/* ==================== SGEMM: C[M,N] = A[M,256] * W[N,256]^T ==================== */
/* BM=BN=64, BK=16, 256 threads, 4x4 per-thread tile. M,N multiples of 64. */
__device__ __forceinline__ void sgemm_body(const float* __restrict__ A,
                                           const float* __restrict__ W,
                                           float* __restrict__ C, int N)
{
    __shared__ float As[16][64];
    __shared__ float Bs[16][64];

    int tid = threadIdx.x;
    int tx = tid & 15, ty = tid >> 4;
    int mBase = blockIdx.x * 64;
    int nBase = blockIdx.y * 64;

    int lr = tid >> 2;            /* 0..63: row within tile      */
    int lc = (tid & 3) << 2;      /* 0,4,8,12: k offset (float4) */
    const float* aP = A + (size_t)(mBase + lr) * MD + lc;
    const float* bP = W + (size_t)(nBase + lr) * MD + lc;

    float acc[4][4];
#pragma unroll
    for (int i = 0; i < 4; i++)
#pragma unroll
        for (int j = 0; j < 4; j++) acc[i][j] = 0.0f;

    for (int k0 = 0; k0 < MD; k0 += 16) {
        float4 av = *(const float4*)(aP + k0);
        float4 bv = *(const float4*)(bP + k0);
        As[lc + 0][lr] = av.x; As[lc + 1][lr] = av.y;
        As[lc + 2][lr] = av.z; As[lc + 3][lr] = av.w;
        Bs[lc + 0][lr] = bv.x; Bs[lc + 1][lr] = bv.y;
        Bs[lc + 2][lr] = bv.z; Bs[lc + 3][lr] = bv.w;
        __syncthreads();
#pragma unroll
        for (int k = 0; k < 16; k++) {
            float4 a = *(const float4*)(&As[k][ty << 2]);
            float4 b = *(const float4*)(&Bs[k][tx << 2]);
            acc[0][0] = fmaf(a.x, b.x, acc[0][0]);
            acc[0][1] = fmaf(a.x, b.y, acc[0][1]);
            acc[0][2] = fmaf(a.x, b.z, acc[0][2]);
            acc[0][3] = fmaf(a.x, b.w, acc[0][3]);
            acc[1][0] = fmaf(a.y, b.x, acc[1][0]);
            acc[1][1] = fmaf(a.y, b.y, acc[1][1]);
            acc[1][2] = fmaf(a.y, b.z, acc[1][2]);
            acc[1][3] = fmaf(a.y, b.w, acc[1][3]);
            acc[2][0] = fmaf(a.z, b.x, acc[2][0]);
            acc[2][1] = fmaf(a.z, b.y, acc[2][1]);
            acc[2][2] = fmaf(a.z, b.z, acc[2][2]);
            acc[2][3] = fmaf(a.z, b.w, acc[2][3]);
            acc[3][0] = fmaf(a.w, b.x, acc[3][0]);
            acc[3][1] = fmaf(a.w, b.y, acc[3][1]);
            acc[3][2] = fmaf(a.w, b.z, acc[3][2]);
            acc[3][3] = fmaf(a.w, b.w, acc[3][3]);
        }
        __syncthreads();
    }
#pragma unroll
    for (int i = 0; i < 4; i++) {
        float4 r = make_float4(acc[i][0], acc[i][1], acc[i][2], acc[i][3]);
        *(float4*)(C + (size_t)(mBase + (ty << 2) + i) * N + nBase + (tx << 2)) = r;
    }
}

__global__ void __launch_bounds__(256) gemm_qkv(const float* __restrict__ W)
{
    sgemm_body(g_xhat, W, g_qkv, QKVD);
}
__global__ void __launch_bounds__(256) gemm_out(const float* __restrict__ W,
                                                float* __restrict__ C)
{
    sgemm_body(g_att, W, C, MD);
}

/* ==================== rotary on 4 consecutive channels [c, c+4) ==================== */
__device__ __forceinline__ float4 rope4(float4 v, float tlx, float tly, int c)
{
    int p0 = c >> 1;               /* pair indices p0, p0+1 */
    float base0 = (p0     < 8) ? tlx : tly;
    float base1 = (p0 + 1 < 8) ? tlx : tly;
    float th0 = base0 * c_invf[p0 & 7];
    float th1 = base1 * c_invf[(p0 + 1) & 7];
    float s0, c0, s1, c1;
    sincosf(th0, &s0, &c0);
    sincosf(th1, &s1, &c1);
    float4 r;
    r.x = v.x * c0 - v.y * s0;
    r.y = v.y * c0 + v.x * s0;
    r.z = v.z * c1 - v.w * s1;
    r.w = v.w * c1 + v.z * s1;
    return r;
}

/* ==================== attention: one block per (b,x,h) ==================== */
__global__ void __launch_bounds__(128) attn_kernel(const int* __restrict__ mask)
{
    int blk = blockIdx.x;
    int h   = blk & 7;
    int bx  = blk >> 3;            /* b*128 + x */
    int x   = bx & 127;
    int t   = threadIdx.x;         /* query row */

    __shared__ float Ks[128][32];
    __shared__ float Vs[128][32];
    __shared__ float mflag[128];

    const float* base = g_qkv + (size_t)bx * S * QKVD;
    float tlx = -1.0f + x * (2.0f / 127.0f);

    /* cooperative K/V tile load (coalesced: 8 consecutive threads = 128B) */
    int d4 = (t & 7) << 2;
    int y0 = t >> 3;
#pragma unroll
    for (int i = 0; i < 8; i++) {
        int y = y0 + i * 16;
        const float* rowp = base + (size_t)y * QKVD + h * HD + d4;
        float4 kv = *(const float4*)(rowp + 256);
        float4 vv = *(const float4*)(rowp + 512);
        if (h == 0) {
            float tly = -1.0f + y * (2.0f / 127.0f);
            kv = rope4(kv, tlx, tly, d4);
        }
        *(float4*)(&Ks[y][d4]) = kv;
        *(float4*)(&Vs[y][d4]) = vv;
    }
    mflag[t] = (mask[bx * S + t] != 0) ? 1.0f : 0.0f;

    /* this thread's q row */
    float q[32];
    {
        const float* qr = base + (size_t)t * QKVD + h * HD;
        float tly = -1.0f + t * (2.0f / 127.0f);
#pragma unroll
        for (int i = 0; i < 8; i++) {
            float4 v = *(const float4*)(qr + i * 4);
            if (h == 0) v = rope4(v, tlx, tly, i * 4);
            q[i * 4 + 0] = v.x; q[i * 4 + 1] = v.y;
            q[i * 4 + 2] = v.z; q[i * 4 + 3] = v.w;
        }
    }
    __syncthreads();

    /* online softmax over 128 keys */
    float m = -INFINITY, l = 0.0f;
    float o[32];
#pragma unroll
    for (int d = 0; d < 32; d++) o[d] = 0.0f;

#pragma unroll 2
    for (int k = 0; k < S; k++) {
        float s = 0.0f;
#pragma unroll
        for (int d = 0; d < 32; d++) s = fmaf(q[d], Ks[k][d], s);
        s = (mflag[k] != 0.0f) ? MBIAS : s * ATT_SCALE;

        float mn   = fmaxf(m, s);
        float corr = __expf(m - mn);
        float p    = __expf(s - mn);
        l = l * corr + p;
#pragma unroll
        for (int d = 0; d < 32; d++) o[d] = fmaf(o[d], corr, p * Vs[k][d]);
        m = mn;
    }

    float inv = 1.0f / l;
    float* op = g_att + ((size_t)bx * S + t) * MD + h * HD;
#pragma unroll
    for (int i = 0; i < 8; i++) {
        float4 r = make_float4(o[i * 4] * inv, o[i * 4 + 1] * inv,
                               o[i * 4 + 2] * inv, o[i * 4 + 3] * inv);
        *(float4*)(op + i * 4) = r;
    }
}

/* ==================== launch ==================== */
extern "C" void kernel_launch(void* const* d_in, const int* in_sizes, int n_in,
                              void* d_out, int out_size)
{
    const float* pair_act  = (const float*)d_in[0];
    const int*   pair_mask = (const int*)d_in[1];
    const float* gamma     = (const float*)d_in[2];
    const float* beta      = (const float*)d_in[3];
    const float* Wqkv      = (const float*)d_in[4];
    const float* Wout      = (const float*)d_in[5];
    float*       out       = (float*)d_out;

    ln_kernel<<<NPOS / 8, 256>>>(pair_act, gamma, beta);

    dim3 g1(NPOS / 64, QKVD / 64);
    gemm_qkv<<<g1, 256>>>(Wqkv);

    attn_kernel<<<BSZ * S * NH, 128>>>(pair_mask);

    dim3 g2(NPOS / 64, MD / 64);
    gemm_out<<<g2, 256>>>(Wout, out);
}

// round 12
// speedup vs baseline: 1.4481x; 1.4481x over previous
#include <cuda_runtime.h>
#include <cuda_bf16.h>
#include <math.h>
#include <stdint.h>

#define S       128
#define BSZ     2
#define MD      256
#define NPOS    (BSZ * S * S)      /* 32768 */
#define QKVD    768
#define HD      32
#define NH      8
#define K3      768                /* split K: [hi | lo | hi] vs [hi | hi | lo] */
#define ATT_SCALE 0.17677669529663687f
#define MBIAS   (-1.0e9f)

/* ---- scratch (static device globals: allocation-free) ---- */
__device__ __nv_bfloat16 g_a2  [(size_t)NPOS * K3];   /* LN out: [ah|al|ah]  50MB */
__device__ float         g_qkv [(size_t)NPOS * QKVD]; /* 100MB */
__device__ __nv_bfloat16 g_att2[(size_t)NPOS * K3];   /* attn out: [oh|ol|oh] 50MB */
__device__ __nv_bfloat16 g_w2qkv[QKVD * K3];          /* [wh|wh|wl] */
__device__ __nv_bfloat16 g_w2out[MD   * K3];

__constant__ float c_invf[8] = {
    1.0f, 0.31622776601683794f, 0.1f, 0.031622776601683794f,
    0.01f, 0.0031622776601683794f, 0.001f, 0.00031622776601683794f
};

/* ==================== helpers ==================== */
__device__ __forceinline__ uint32_t smem_u32(const void* p) {
    uint32_t a;
    asm("{ .reg .u64 t; cvta.to.shared.u64 t, %1; cvt.u32.u64 %0, t; }" : "=r"(a) : "l"(p));
    return a;
}
__device__ __forceinline__ void ldmx4(uint32_t& r0, uint32_t& r1, uint32_t& r2, uint32_t& r3,
                                      uint32_t addr) {
    asm volatile("ldmatrix.sync.aligned.m8n8.x4.shared.b16 {%0,%1,%2,%3}, [%4];"
                 : "=r"(r0), "=r"(r1), "=r"(r2), "=r"(r3) : "r"(addr));
}
__device__ __forceinline__ void ldmx2(uint32_t& r0, uint32_t& r1, uint32_t addr) {
    asm volatile("ldmatrix.sync.aligned.m8n8.x2.shared.b16 {%0,%1}, [%2];"
                 : "=r"(r0), "=r"(r1) : "r"(addr));
}
__device__ __forceinline__ void mma16816(float* d, const uint32_t* a, const uint32_t* b) {
    asm volatile("mma.sync.aligned.m16n8k16.row.col.f32.bf16.bf16.f32 "
                 "{%0,%1,%2,%3}, {%4,%5,%6,%7}, {%8,%9}, {%0,%1,%2,%3};"
                 : "+f"(d[0]), "+f"(d[1]), "+f"(d[2]), "+f"(d[3])
                 : "r"(a[0]), "r"(a[1]), "r"(a[2]), "r"(a[3]), "r"(b[0]), "r"(b[1]));
}
#define CP16(dst, src)  asm volatile("cp.async.cg.shared.global [%0], [%1], 16;" :: "r"(dst), "l"(src))
#define CP_COMMIT()     asm volatile("cp.async.commit_group;" ::: "memory")
#define CP_WAIT(n)      asm volatile("cp.async.wait_group %0;" :: "n"(n) : "memory")

/* ==================== split helper ==================== */
__device__ __forceinline__ void split_pair(float a, float b, __nv_bfloat162* hi, __nv_bfloat162* lo) {
    __nv_bfloat16 h0 = __float2bfloat16(a);
    __nv_bfloat16 h1 = __float2bfloat16(b);
    __nv_bfloat16 l0 = __float2bfloat16(a - __bfloat162float(h0));
    __nv_bfloat16 l1 = __float2bfloat16(b - __bfloat162float(h1));
    *hi = __nv_bfloat162(h0, h1);
    *lo = __nv_bfloat162(l0, l1);
}

/* ==================== LayerNorm + 3-block split ==================== */
__global__ void __launch_bounds__(256) ln_kernel(const float* __restrict__ x,
                                                 const float* __restrict__ gamma,
                                                 const float* __restrict__ beta)
{
    int row  = blockIdx.x * 8 + (threadIdx.x >> 5);
    int lane = threadIdx.x & 31;
    const float* xr = x + (size_t)row * MD;

    float4 a = *(const float4*)(xr + lane * 4);
    float4 b = *(const float4*)(xr + 128 + lane * 4);

    float s  = a.x + a.y + a.z + a.w + b.x + b.y + b.z + b.w;
    float ss = a.x*a.x + a.y*a.y + a.z*a.z + a.w*a.w
             + b.x*b.x + b.y*b.y + b.z*b.z + b.w*b.w;
#pragma unroll
    for (int o = 16; o > 0; o >>= 1) {
        s  += __shfl_xor_sync(0xffffffffu, s,  o);
        ss += __shfl_xor_sync(0xffffffffu, ss, o);
    }
    float mu   = s  * (1.0f / 256.0f);
    float var  = ss * (1.0f / 256.0f) - mu * mu;
    float rstd = rsqrtf(var + 1e-5f);

    float4 g0 = *(const float4*)(gamma + lane * 4);
    float4 g1 = *(const float4*)(gamma + 128 + lane * 4);
    float4 b0 = *(const float4*)(beta  + lane * 4);
    float4 b1 = *(const float4*)(beta  + 128 + lane * 4);

    float r00 = (a.x - mu) * rstd * g0.x + b0.x;
    float r01 = (a.y - mu) * rstd * g0.y + b0.y;
    float r02 = (a.z - mu) * rstd * g0.z + b0.z;
    float r03 = (a.w - mu) * rstd * g0.w + b0.w;
    float r10 = (b.x - mu) * rstd * g1.x + b1.x;
    float r11 = (b.y - mu) * rstd * g1.y + b1.y;
    float r12 = (b.z - mu) * rstd * g1.z + b1.z;
    float r13 = (b.w - mu) * rstd * g1.w + b1.w;

    __nv_bfloat16* orow = g_a2 + (size_t)row * K3;
    __nv_bfloat162 h, l;
#define PUT(c, hh, ll) do { \
        *(__nv_bfloat162*)(orow + (c))       = (hh); \
        *(__nv_bfloat162*)(orow + 512 + (c)) = (hh); \
        *(__nv_bfloat162*)(orow + 256 + (c)) = (ll); } while (0)
    split_pair(r00, r01, &h, &l);  PUT(lane*4,           h, l);
    split_pair(r02, r03, &h, &l);  PUT(lane*4 + 2,       h, l);
    split_pair(r10, r11, &h, &l);  PUT(128 + lane*4,     h, l);
    split_pair(r12, r13, &h, &l);  PUT(128 + lane*4 + 2, h, l);
#undef PUT
}

/* ==================== weight split: [wh | wh | wl] ==================== */
__global__ void __launch_bounds__(256) wconv_kernel(const float* __restrict__ Wqkv,
                                                    const float* __restrict__ Wout)
{
    int i = blockIdx.x * 256 + threadIdx.x;   /* grid covers QKVD*MD */
    int n = i >> 8, k = i & 255;
    {
        float w = Wqkv[i];
        __nv_bfloat16 hi = __float2bfloat16(w);
        __nv_bfloat16 lo = __float2bfloat16(w - __bfloat162float(hi));
        g_w2qkv[(size_t)n * K3 + k]       = hi;
        g_w2qkv[(size_t)n * K3 + 256 + k] = hi;
        g_w2qkv[(size_t)n * K3 + 512 + k] = lo;
    }
    if (i < MD * MD) {
        float w = Wout[i];
        __nv_bfloat16 hi = __float2bfloat16(w);
        __nv_bfloat16 lo = __float2bfloat16(w - __bfloat162float(hi));
        g_w2out[(size_t)n * K3 + k]       = hi;
        g_w2out[(size_t)n * K3 + 256 + k] = hi;
        g_w2out[(size_t)n * K3 + 512 + k] = lo;
    }
}

/* ==================== mma.sync GEMM: C[M,N] = A2[M,768] * W2[N,768]^T ========
   Block tile 128x128, BK=32, 8 warps (warp tile 32x64), cp.async double buffer. */
#define BK      32
#define PITCH   80                  /* 32 bf16 = 64B data, padded to 80B */
#define ASTG    (128 * PITCH)       /* 10240 */
#define STG     (2 * ASTG)          /* 20480 per stage (A+B) */
#define ROWB    (K3 * 2)            /* 1536 B gmem row stride */

__device__ __forceinline__ void mma_gemm_body(const __nv_bfloat16* __restrict__ A2,
                                              const __nv_bfloat16* __restrict__ W2,
                                              float* __restrict__ C, int N)
{
    __shared__ __align__(16) char sm[2 * STG];   /* 40 KB */
    uint32_t sbase = smem_u32(sm);

    int tid  = threadIdx.x;
    int wid  = tid >> 5;
    int lane = tid & 31;
    int mBase = blockIdx.x * 128, nBase = blockIdx.y * 128;
    int wm = (wid & 3) * 32;        /* warp row offset */
    int wn = (wid >> 2) * 64;       /* warp col offset */

    const char* Abase = (const char*)(A2 + (size_t)mBase * K3);
    const char* Bbase = (const char*)(W2 + (size_t)nBase * K3);

    int r0 = tid >> 2;              /* 0..63 */
    int cc = (tid & 3) * 16;        /* 0,16,32,48 */

#define LOAD_STAGE(sidx, k0)  do {                                                     \
        uint32_t sb_ = sbase + (sidx) * STG;                                           \
        size_t ko_ = (size_t)(k0) * 2;                                                 \
        CP16(sb_ + r0 * PITCH + cc,               Abase + (size_t)r0 * ROWB + ko_ + cc); \
        CP16(sb_ + (r0 + 64) * PITCH + cc,        Abase + (size_t)(r0 + 64) * ROWB + ko_ + cc); \
        CP16(sb_ + ASTG + r0 * PITCH + cc,        Bbase + (size_t)r0 * ROWB + ko_ + cc); \
        CP16(sb_ + ASTG + (r0 + 64) * PITCH + cc, Bbase + (size_t)(r0 + 64) * ROWB + ko_ + cc); \
        CP_COMMIT();                                                                   \
    } while (0)

    float acc[2][8][4];
#pragma unroll
    for (int mi = 0; mi < 2; mi++)
#pragma unroll
        for (int ni = 0; ni < 8; ni++)
#pragma unroll
            for (int j = 0; j < 4; j++) acc[mi][ni][j] = 0.0f;

    LOAD_STAGE(0, 0);

    for (int it = 0; it < 24; it++) {
        if (it < 23) { LOAD_STAGE((it + 1) & 1, (it + 1) * BK); CP_WAIT(1); }
        else         { CP_WAIT(0); }
        __syncthreads();

        uint32_t sb = sbase + (it & 1) * STG;
#pragma unroll
        for (int kk = 0; kk < 2; kk++) {
            uint32_t a[2][4], b[8][2];
#pragma unroll
            for (int mi = 0; mi < 2; mi++) {
                uint32_t addr = sb + (uint32_t)(wm + mi * 16 + (lane & 15)) * PITCH
                              + (uint32_t)((lane >> 4) * 8 + kk * 16) * 2;
                ldmx4(a[mi][0], a[mi][1], a[mi][2], a[mi][3], addr);
            }
#pragma unroll
            for (int ni = 0; ni < 8; ni++) {
                uint32_t addr = sb + ASTG
                              + (uint32_t)(wn + ni * 8 + (lane & 7)) * PITCH
                              + (uint32_t)(((lane >> 3) & 1) * 8 + kk * 16) * 2;
                ldmx2(b[ni][0], b[ni][1], addr);
            }
#pragma unroll
            for (int mi = 0; mi < 2; mi++)
#pragma unroll
                for (int ni = 0; ni < 8; ni++)
                    mma16816(acc[mi][ni], a[mi], b[ni]);
        }
        __syncthreads();
    }

    /* epilogue */
    int trow = lane >> 2, tcol = (lane & 3) * 2;
#pragma unroll
    for (int mi = 0; mi < 2; mi++) {
#pragma unroll
        for (int ni = 0; ni < 8; ni++) {
            float* cp0 = C + (size_t)(mBase + wm + mi * 16 + trow) * N
                       + nBase + wn + ni * 8 + tcol;
            cp0[0] = acc[mi][ni][0];
            cp0[1] = acc[mi][ni][1];
            float* cp1 = cp0 + 8 * (size_t)N;
            cp1[0] = acc[mi][ni][2];
            cp1[1] = acc[mi][ni][3];
        }
    }
#undef LOAD_STAGE
}

__global__ void __launch_bounds__(256) gemm_qkv_mma()
{
    mma_gemm_body(g_a2, g_w2qkv, g_qkv, QKVD);
}
__global__ void __launch_bounds__(256) gemm_out_mma(float* __restrict__ C)
{
    mma_gemm_body(g_att2, g_w2out, C, MD);
}

/* ==================== rotary ==================== */
__device__ __forceinline__ float4 rope4(float4 v, float tlx, float tly, int c)
{
    int p0 = c >> 1;
    float base0 = (p0     < 8) ? tlx : tly;
    float base1 = (p0 + 1 < 8) ? tlx : tly;
    float th0 = base0 * c_invf[p0 & 7];
    float th1 = base1 * c_invf[(p0 + 1) & 7];
    float s0, c0, s1, c1;
    sincosf(th0, &s0, &c0);
    sincosf(th1, &s1, &c1);
    float4 r;
    r.x = v.x * c0 - v.y * s0;
    r.y = v.y * c0 + v.x * s0;
    r.z = v.z * c1 - v.w * s1;
    r.w = v.w * c1 + v.z * s1;
    return r;
}

/* ==================== attention: one block per (b,x,h) ==================== */
__global__ void __launch_bounds__(128) attn_kernel(const int* __restrict__ mask)
{
    int blk = blockIdx.x;
    int h   = blk & 7;
    int bx  = blk >> 3;
    int x   = bx & 127;
    int t   = threadIdx.x;

    __shared__ float Ks[128][32];
    __shared__ float Vs[128][32];
    __shared__ float mflag[128];

    const float* base = g_qkv + (size_t)bx * S * QKVD;
    float tlx = -1.0f + x * (2.0f / 127.0f);

    int d4 = (t & 7) << 2;
    int y0 = t >> 3;
#pragma unroll
    for (int i = 0; i < 8; i++) {
        int y = y0 + i * 16;
        const float* rowp = base + (size_t)y * QKVD + h * HD + d4;
        float4 kv = *(const float4*)(rowp + 256);
        float4 vv = *(const float4*)(rowp + 512);
        if (h == 0) {
            float tly = -1.0f + y * (2.0f / 127.0f);
            kv = rope4(kv, tlx, tly, d4);
        }
        *(float4*)(&Ks[y][d4]) = kv;
        *(float4*)(&Vs[y][d4]) = vv;
    }
    mflag[t] = (mask[bx * S + t] != 0) ? 1.0f : 0.0f;

    float q[32];
    {
        const float* qr = base + (size_t)t * QKVD + h * HD;
        float tly = -1.0f + t * (2.0f / 127.0f);
#pragma unroll
        for (int i = 0; i < 8; i++) {
            float4 v = *(const float4*)(qr + i * 4);
            if (h == 0) v = rope4(v, tlx, tly, i * 4);
            q[i*4+0] = v.x; q[i*4+1] = v.y; q[i*4+2] = v.z; q[i*4+3] = v.w;
        }
    }
    __syncthreads();

    float m = -INFINITY, l = 0.0f;
    float o[32];
#pragma unroll
    for (int d = 0; d < 32; d++) o[d] = 0.0f;

#pragma unroll 2
    for (int k = 0; k < S; k++) {
        float s = 0.0f;
#pragma unroll
        for (int d = 0; d < 32; d++) s = fmaf(q[d], Ks[k][d], s);
        s = (mflag[k] != 0.0f) ? MBIAS : s * ATT_SCALE;

        float mn   = fmaxf(m, s);
        float corr = __expf(m - mn);
        float p    = __expf(s - mn);
        l = l * corr + p;
#pragma unroll
        for (int d = 0; d < 32; d++) o[d] = fmaf(o[d], corr, p * Vs[k][d]);
        m = mn;
    }

    float inv = 1.0f / l;
    __nv_bfloat16* op = g_att2 + ((size_t)bx * S + t) * K3 + h * HD;
#pragma unroll
    for (int i = 0; i < 32; i += 2) {
        __nv_bfloat162 hp, lp;
        split_pair(o[i] * inv, o[i+1] * inv, &hp, &lp);
        *(__nv_bfloat162*)(op + i)       = hp;
        *(__nv_bfloat162*)(op + 512 + i) = hp;
        *(__nv_bfloat162*)(op + 256 + i) = lp;
    }
}

/* ==================== launch ==================== */
extern "C" void kernel_launch(void* const* d_in, const int* in_sizes, int n_in,
                              void* d_out, int out_size)
{
    const float* pair_act  = (const float*)d_in[0];
    const int*   pair_mask = (const int*)d_in[1];
    const float* gamma     = (const float*)d_in[2];
    const float* beta      = (const float*)d_in[3];
    const float* Wqkv      = (const float*)d_in[4];
    const float* Wout      = (const float*)d_in[5];
    float*       out       = (float*)d_out;

    ln_kernel<<<NPOS / 8, 256>>>(pair_act, gamma, beta);
    wconv_kernel<<<(QKVD * MD) / 256, 256>>>(Wqkv, Wout);

    dim3 g1(NPOS / 128, QKVD / 128);
    gemm_qkv_mma<<<g1, 256>>>();

    attn_kernel<<<BSZ * S * NH, 128>>>(pair_mask);

    dim3 g2(NPOS / 128, MD / 128);
    gemm_out_mma<<<g2, 256>>>(out);
}

// round 13
// speedup vs baseline: 1.9480x; 1.3453x over previous
#include <cuda_runtime.h>
#include <cuda_fp16.h>
#include <math.h>
#include <stdint.h>

#define S       128
#define BSZ     2
#define MD      256
#define NPOS    (BSZ * S * S)      /* 32768 */
#define QKVD    768
#define HD      32
#define NH      8
#define K2      512                /* split K: A=[ah|al], W=[wh|wh] */
#define ATT_SCALE 0.17677669529663687f
#define MBIAS   (-1.0e9f)

/* ---- scratch (static device globals: allocation-free) ---- */
__device__ __half g_a2  [(size_t)NPOS * K2];   /* LN out [ah|al]   33.5MB */
__device__ float  g_qkv [(size_t)NPOS * QKVD]; /* 100MB */
__device__ __half g_att2[(size_t)NPOS * K2];   /* attn out [oh|ol] 33.5MB */
__device__ __half g_w2qkv[QKVD * K2];          /* [wh|wh] */
__device__ __half g_w2out[MD   * K2];

__constant__ float c_invf[8] = {
    1.0f, 0.31622776601683794f, 0.1f, 0.031622776601683794f,
    0.01f, 0.0031622776601683794f, 0.001f, 0.00031622776601683794f
};

/* ==================== helpers ==================== */
__device__ __forceinline__ uint32_t smem_u32(const void* p) {
    uint32_t a;
    asm("{ .reg .u64 t; cvta.to.shared.u64 t, %1; cvt.u32.u64 %0, t; }" : "=r"(a) : "l"(p));
    return a;
}
__device__ __forceinline__ void ldmx4(uint32_t& r0, uint32_t& r1, uint32_t& r2, uint32_t& r3,
                                      uint32_t addr) {
    asm volatile("ldmatrix.sync.aligned.m8n8.x4.shared.b16 {%0,%1,%2,%3}, [%4];"
                 : "=r"(r0), "=r"(r1), "=r"(r2), "=r"(r3) : "r"(addr));
}
__device__ __forceinline__ void ldmx2(uint32_t& r0, uint32_t& r1, uint32_t addr) {
    asm volatile("ldmatrix.sync.aligned.m8n8.x2.shared.b16 {%0,%1}, [%2];"
                 : "=r"(r0), "=r"(r1) : "r"(addr));
}
__device__ __forceinline__ void mma16816(float* d, const uint32_t* a, const uint32_t* b) {
    asm volatile("mma.sync.aligned.m16n8k16.row.col.f32.f16.f16.f32 "
                 "{%0,%1,%2,%3}, {%4,%5,%6,%7}, {%8,%9}, {%0,%1,%2,%3};"
                 : "+f"(d[0]), "+f"(d[1]), "+f"(d[2]), "+f"(d[3])
                 : "r"(a[0]), "r"(a[1]), "r"(a[2]), "r"(a[3]), "r"(b[0]), "r"(b[1]));
}
#define CP16(dst, src)  asm volatile("cp.async.cg.shared.global [%0], [%1], 16;" :: "r"(dst), "l"(src))
#define CP_COMMIT()     asm volatile("cp.async.commit_group;" ::: "memory")
#define CP_WAIT(n)      asm volatile("cp.async.wait_group %0;" :: "n"(n) : "memory")

/* ==================== fp16 split helper ==================== */
__device__ __forceinline__ void split_pair_h(float a, float b, __half2* hi, __half2* lo) {
    __half h0 = __float2half_rn(a);
    __half h1 = __float2half_rn(b);
    __half l0 = __float2half_rn(a - __half2float(h0));
    __half l1 = __float2half_rn(b - __half2float(h1));
    *hi = __half2(h0, h1);
    *lo = __half2(l0, l1);
}

/* ==================== LayerNorm + fp16 2-block split ==================== */
__global__ void __launch_bounds__(256) ln_kernel(const float* __restrict__ x,
                                                 const float* __restrict__ gamma,
                                                 const float* __restrict__ beta)
{
    int row  = blockIdx.x * 8 + (threadIdx.x >> 5);
    int lane = threadIdx.x & 31;
    const float* xr = x + (size_t)row * MD;

    float4 a = *(const float4*)(xr + lane * 4);
    float4 b = *(const float4*)(xr + 128 + lane * 4);

    float s  = a.x + a.y + a.z + a.w + b.x + b.y + b.z + b.w;
    float ss = a.x*a.x + a.y*a.y + a.z*a.z + a.w*a.w
             + b.x*b.x + b.y*b.y + b.z*b.z + b.w*b.w;
#pragma unroll
    for (int o = 16; o > 0; o >>= 1) {
        s  += __shfl_xor_sync(0xffffffffu, s,  o);
        ss += __shfl_xor_sync(0xffffffffu, ss, o);
    }
    float mu   = s  * (1.0f / 256.0f);
    float var  = ss * (1.0f / 256.0f) - mu * mu;
    float rstd = rsqrtf(var + 1e-5f);

    float4 g0 = *(const float4*)(gamma + lane * 4);
    float4 g1 = *(const float4*)(gamma + 128 + lane * 4);
    float4 b0 = *(const float4*)(beta  + lane * 4);
    float4 b1 = *(const float4*)(beta  + 128 + lane * 4);

    float r00 = (a.x - mu) * rstd * g0.x + b0.x;
    float r01 = (a.y - mu) * rstd * g0.y + b0.y;
    float r02 = (a.z - mu) * rstd * g0.z + b0.z;
    float r03 = (a.w - mu) * rstd * g0.w + b0.w;
    float r10 = (b.x - mu) * rstd * g1.x + b1.x;
    float r11 = (b.y - mu) * rstd * g1.y + b1.y;
    float r12 = (b.z - mu) * rstd * g1.z + b1.z;
    float r13 = (b.w - mu) * rstd * g1.w + b1.w;

    __half* orow = g_a2 + (size_t)row * K2;
    __half2 h, l;
#define PUT(c, hh, ll) do { \
        *(__half2*)(orow + (c))       = (hh); \
        *(__half2*)(orow + 256 + (c)) = (ll); } while (0)
    split_pair_h(r00, r01, &h, &l);  PUT(lane*4,           h, l);
    split_pair_h(r02, r03, &h, &l);  PUT(lane*4 + 2,       h, l);
    split_pair_h(r10, r11, &h, &l);  PUT(128 + lane*4,     h, l);
    split_pair_h(r12, r13, &h, &l);  PUT(128 + lane*4 + 2, h, l);
#undef PUT
}

/* ==================== weight: [wh | wh] (hi duplicated) ==================== */
__global__ void __launch_bounds__(256) wconv_kernel(const float* __restrict__ Wqkv,
                                                    const float* __restrict__ Wout)
{
    int i = blockIdx.x * 256 + threadIdx.x;   /* grid covers QKVD*MD */
    int n = i >> 8, k = i & 255;
    {
        __half hi = __float2half_rn(Wqkv[i]);
        g_w2qkv[(size_t)n * K2 + k]       = hi;
        g_w2qkv[(size_t)n * K2 + 256 + k] = hi;
    }
    if (i < MD * MD) {
        __half hi = __float2half_rn(Wout[i]);
        g_w2out[(size_t)n * K2 + k]       = hi;
        g_w2out[(size_t)n * K2 + 256 + k] = hi;
    }
}

/* ==================== mma.sync GEMM: C[M,N] = A2[M,512] * W2[N,512]^T ========
   Block tile 128x128, BK=32, 8 warps (warp tile 32x64), cp.async double buffer. */
#define BK      32
#define PITCH   80                  /* 32 fp16 = 64B data, padded to 80B */
#define ASTG    (128 * PITCH)       /* 10240 */
#define STG     (2 * ASTG)          /* 20480 per stage (A+B) */
#define ROWB    (K2 * 2)            /* 1024 B gmem row stride */
#define KIT     (K2 / BK)           /* 16 iterations */

__device__ __forceinline__ void mma_gemm_body(const __half* __restrict__ A2,
                                              const __half* __restrict__ W2,
                                              float* __restrict__ C, int N)
{
    __shared__ __align__(16) char sm[2 * STG];   /* 40 KB */
    uint32_t sbase = smem_u32(sm);

    int tid  = threadIdx.x;
    int wid  = tid >> 5;
    int lane = tid & 31;
    int mBase = blockIdx.x * 128, nBase = blockIdx.y * 128;
    int wm = (wid & 3) * 32;        /* warp row offset */
    int wn = (wid >> 2) * 64;       /* warp col offset */

    const char* Abase = (const char*)(A2 + (size_t)mBase * K2);
    const char* Bbase = (const char*)(W2 + (size_t)nBase * K2);

    int r0 = tid >> 2;              /* 0..63 */
    int cc = (tid & 3) * 16;        /* 0,16,32,48 */

#define LOAD_STAGE(sidx, k0)  do {                                                     \
        uint32_t sb_ = sbase + (sidx) * STG;                                           \
        size_t ko_ = (size_t)(k0) * 2;                                                 \
        CP16(sb_ + r0 * PITCH + cc,               Abase + (size_t)r0 * ROWB + ko_ + cc); \
        CP16(sb_ + (r0 + 64) * PITCH + cc,        Abase + (size_t)(r0 + 64) * ROWB + ko_ + cc); \
        CP16(sb_ + ASTG + r0 * PITCH + cc,        Bbase + (size_t)r0 * ROWB + ko_ + cc); \
        CP16(sb_ + ASTG + (r0 + 64) * PITCH + cc, Bbase + (size_t)(r0 + 64) * ROWB + ko_ + cc); \
        CP_COMMIT();                                                                   \
    } while (0)

    float acc[2][8][4];
#pragma unroll
    for (int mi = 0; mi < 2; mi++)
#pragma unroll
        for (int ni = 0; ni < 8; ni++)
#pragma unroll
            for (int j = 0; j < 4; j++) acc[mi][ni][j] = 0.0f;

    LOAD_STAGE(0, 0);

    for (int it = 0; it < KIT; it++) {
        if (it < KIT - 1) { LOAD_STAGE((it + 1) & 1, (it + 1) * BK); CP_WAIT(1); }
        else              { CP_WAIT(0); }
        __syncthreads();

        uint32_t sb = sbase + (it & 1) * STG;
#pragma unroll
        for (int kk = 0; kk < 2; kk++) {
            uint32_t a[2][4], b[8][2];
#pragma unroll
            for (int mi = 0; mi < 2; mi++) {
                uint32_t addr = sb + (uint32_t)(wm + mi * 16 + (lane & 15)) * PITCH
                              + (uint32_t)((lane >> 4) * 8 + kk * 16) * 2;
                ldmx4(a[mi][0], a[mi][1], a[mi][2], a[mi][3], addr);
            }
#pragma unroll
            for (int ni = 0; ni < 8; ni++) {
                uint32_t addr = sb + ASTG
                              + (uint32_t)(wn + ni * 8 + (lane & 7)) * PITCH
                              + (uint32_t)(((lane >> 3) & 1) * 8 + kk * 16) * 2;
                ldmx2(b[ni][0], b[ni][1], addr);
            }
#pragma unroll
            for (int mi = 0; mi < 2; mi++)
#pragma unroll
                for (int ni = 0; ni < 8; ni++)
                    mma16816(acc[mi][ni], a[mi], b[ni]);
        }
        __syncthreads();
    }

    /* epilogue */
    int trow = lane >> 2, tcol = (lane & 3) * 2;
#pragma unroll
    for (int mi = 0; mi < 2; mi++) {
#pragma unroll
        for (int ni = 0; ni < 8; ni++) {
            float* cp0 = C + (size_t)(mBase + wm + mi * 16 + trow) * N
                       + nBase + wn + ni * 8 + tcol;
            cp0[0] = acc[mi][ni][0];
            cp0[1] = acc[mi][ni][1];
            float* cp1 = cp0 + 8 * (size_t)N;
            cp1[0] = acc[mi][ni][2];
            cp1[1] = acc[mi][ni][3];
        }
    }
#undef LOAD_STAGE
}

__global__ void __launch_bounds__(256) gemm_qkv_mma()
{
    mma_gemm_body(g_a2, g_w2qkv, g_qkv, QKVD);
}
__global__ void __launch_bounds__(256) gemm_out_mma(float* __restrict__ C)
{
    mma_gemm_body(g_att2, g_w2out, C, MD);
}

/* ==================== rotary ==================== */
__device__ __forceinline__ float4 rope4(float4 v, float tlx, float tly, int c)
{
    int p0 = c >> 1;
    float base0 = (p0     < 8) ? tlx : tly;
    float base1 = (p0 + 1 < 8) ? tlx : tly;
    float th0 = base0 * c_invf[p0 & 7];
    float th1 = base1 * c_invf[(p0 + 1) & 7];
    float s0, c0, s1, c1;
    sincosf(th0, &s0, &c0);
    sincosf(th1, &s1, &c1);
    float4 r;
    r.x = v.x * c0 - v.y * s0;
    r.y = v.y * c0 + v.x * s0;
    r.z = v.z * c1 - v.w * s1;
    r.w = v.w * c1 + v.z * s1;
    return r;
}

/* ==================== attention: one block per (b,x,h), chunked ============ */
__global__ void __launch_bounds__(128, 5) attn_kernel(const int* __restrict__ mask)
{
    int blk = blockIdx.x;
    int h   = blk & 7;
    int bx  = blk >> 3;
    int x   = bx & 127;
    int t   = threadIdx.x;

    __shared__ float Ks[128][32];
    __shared__ float Vs[128][32];
    __shared__ float mflag[128];

    const float* base = g_qkv + (size_t)bx * S * QKVD;
    float tlx = -1.0f + x * (2.0f / 127.0f);

    int d4 = (t & 7) << 2;
    int y0 = t >> 3;
#pragma unroll
    for (int i = 0; i < 8; i++) {
        int y = y0 + i * 16;
        const float* rowp = base + (size_t)y * QKVD + h * HD + d4;
        float4 kv = *(const float4*)(rowp + 256);
        float4 vv = *(const float4*)(rowp + 512);
        if (h == 0) {
            float tly = -1.0f + y * (2.0f / 127.0f);
            kv = rope4(kv, tlx, tly, d4);
        }
        *(float4*)(&Ks[y][d4]) = kv;
        *(float4*)(&Vs[y][d4]) = vv;
    }
    mflag[t] = (mask[bx * S + t] != 0) ? 1.0f : 0.0f;

    /* this thread's q row, as float4[8] */
    float4 qv[8];
    {
        const float* qr = base + (size_t)t * QKVD + h * HD;
        float tly = -1.0f + t * (2.0f / 127.0f);
#pragma unroll
        for (int i = 0; i < 8; i++) {
            float4 v = *(const float4*)(qr + i * 4);
            if (h == 0) v = rope4(v, tlx, tly, i * 4);
            qv[i] = v;
        }
    }
    __syncthreads();

    float m = -INFINITY, l = 0.0f;
    float4 ov[8];
#pragma unroll
    for (int i = 0; i < 8; i++) ov[i] = make_float4(0.f, 0.f, 0.f, 0.f);

    for (int c = 0; c < 16; c++) {
        int k0 = c * 8;
        float sc[8];
#pragma unroll
        for (int j = 0; j < 8; j++) {
            const float4* kr = (const float4*)(&Ks[k0 + j][0]);
            float s = 0.0f;
#pragma unroll
            for (int i = 0; i < 8; i++) {
                float4 k4 = kr[i];
                s = fmaf(qv[i].x, k4.x, s);
                s = fmaf(qv[i].y, k4.y, s);
                s = fmaf(qv[i].z, k4.z, s);
                s = fmaf(qv[i].w, k4.w, s);
            }
            sc[j] = (mflag[k0 + j] != 0.0f) ? MBIAS : s * ATT_SCALE;
        }

        float cm = sc[0];
#pragma unroll
        for (int j = 1; j < 8; j++) cm = fmaxf(cm, sc[j]);
        float mn   = fmaxf(m, cm);
        float corr = __expf(m - mn);

        float psum = 0.0f;
#pragma unroll
        for (int j = 0; j < 8; j++) {
            sc[j] = __expf(sc[j] - mn);
            psum += sc[j];
        }
        l = l * corr + psum;

#pragma unroll
        for (int i = 0; i < 8; i++) {
            float4 acc = ov[i];
            acc.x *= corr; acc.y *= corr; acc.z *= corr; acc.w *= corr;
#pragma unroll
            for (int j = 0; j < 8; j++) {
                float4 v = *(const float4*)(&Vs[k0 + j][i * 4]);
                float p = sc[j];
                acc.x = fmaf(p, v.x, acc.x);
                acc.y = fmaf(p, v.y, acc.y);
                acc.z = fmaf(p, v.z, acc.z);
                acc.w = fmaf(p, v.w, acc.w);
            }
            ov[i] = acc;
        }
        m = mn;
    }

    float inv = 1.0f / l;
    __half* op = g_att2 + ((size_t)bx * S + t) * K2 + h * HD;
#pragma unroll
    for (int i = 0; i < 8; i++) {
        __half2 hp, lp;
        split_pair_h(ov[i].x * inv, ov[i].y * inv, &hp, &lp);
        *(__half2*)(op + i * 4)       = hp;
        *(__half2*)(op + 256 + i * 4) = lp;
        split_pair_h(ov[i].z * inv, ov[i].w * inv, &hp, &lp);
        *(__half2*)(op + i * 4 + 2)       = hp;
        *(__half2*)(op + 256 + i * 4 + 2) = lp;
    }
}

/* ==================== launch ==================== */
extern "C" void kernel_launch(void* const* d_in, const int* in_sizes, int n_in,
                              void* d_out, int out_size)
{
    const float* pair_act  = (const float*)d_in[0];
    const int*   pair_mask = (const int*)d_in[1];
    const float* gamma     = (const float*)d_in[2];
    const float* beta      = (const float*)d_in[3];
    const float* Wqkv      = (const float*)d_in[4];
    const float* Wout      = (const float*)d_in[5];
    float*       out       = (float*)d_out;

    ln_kernel<<<NPOS / 8, 256>>>(pair_act, gamma, beta);
    wconv_kernel<<<(QKVD * MD) / 256, 256>>>(Wqkv, Wout);

    dim3 g1(NPOS / 128, QKVD / 128);
    gemm_qkv_mma<<<g1, 256>>>();

    attn_kernel<<<BSZ * S * NH, 128>>>(pair_mask);

    dim3 g2(NPOS / 128, MD / 128);
    gemm_out_mma<<<g2, 256>>>(out);
}

// round 14
// speedup vs baseline: 2.0346x; 1.0444x over previous
#include <cuda_runtime.h>
#include <cuda_fp16.h>
#include <math.h>
#include <stdint.h>

#define S       128
#define BSZ     2
#define MD      256
#define NPOS    (BSZ * S * S)      /* 32768 */
#define QKVD    768
#define HD      32
#define NH      8
#define K2      512                /* split K: A=[ah|al], W=[wh|wh] */
#define ATT_SCALE 0.17677669529663687f
#define MBIAS   (-1.0e9f)

/* ---- scratch (static device globals: allocation-free) ---- */
__device__ __half g_a2  [(size_t)NPOS * K2];   /* LN out [ah|al]   33.5MB */
__device__ __half g_qk16[(size_t)NPOS * 512];  /* q(0..255)|k(256..511) fp16 33.5MB */
__device__ float  g_v   [(size_t)NPOS * MD];   /* v fp32 33.5MB */
__device__ __half g_att2[(size_t)NPOS * K2];   /* attn out [oh|ol] 33.5MB */
__device__ __half g_w2qkv[QKVD * K2];          /* [wh|wh] */
__device__ __half g_w2out[MD   * K2];

__constant__ float c_invf[8] = {
    1.0f, 0.31622776601683794f, 0.1f, 0.031622776601683794f,
    0.01f, 0.0031622776601683794f, 0.001f, 0.00031622776601683794f
};

/* ==================== helpers ==================== */
__device__ __forceinline__ uint32_t smem_u32(const void* p) {
    uint32_t a;
    asm("{ .reg .u64 t; cvta.to.shared.u64 t, %1; cvt.u32.u64 %0, t; }" : "=r"(a) : "l"(p));
    return a;
}
__device__ __forceinline__ void ldmx4(uint32_t& r0, uint32_t& r1, uint32_t& r2, uint32_t& r3,
                                      uint32_t addr) {
    asm volatile("ldmatrix.sync.aligned.m8n8.x4.shared.b16 {%0,%1,%2,%3}, [%4];"
                 : "=r"(r0), "=r"(r1), "=r"(r2), "=r"(r3) : "r"(addr));
}
__device__ __forceinline__ void ldmx2(uint32_t& r0, uint32_t& r1, uint32_t addr) {
    asm volatile("ldmatrix.sync.aligned.m8n8.x2.shared.b16 {%0,%1}, [%2];"
                 : "=r"(r0), "=r"(r1) : "r"(addr));
}
__device__ __forceinline__ void mma16816(float* d, const uint32_t* a, const uint32_t* b) {
    asm volatile("mma.sync.aligned.m16n8k16.row.col.f32.f16.f16.f32 "
                 "{%0,%1,%2,%3}, {%4,%5,%6,%7}, {%8,%9}, {%0,%1,%2,%3};"
                 : "+f"(d[0]), "+f"(d[1]), "+f"(d[2]), "+f"(d[3])
                 : "r"(a[0]), "r"(a[1]), "r"(a[2]), "r"(a[3]), "r"(b[0]), "r"(b[1]));
}
#define CP16(dst, src)  asm volatile("cp.async.cg.shared.global [%0], [%1], 16;" :: "r"(dst), "l"(src))
#define CP_COMMIT()     asm volatile("cp.async.commit_group;" ::: "memory")
#define CP_WAIT(n)      asm volatile("cp.async.wait_group %0;" :: "n"(n) : "memory")

/* ==================== fp16 split helper ==================== */
__device__ __forceinline__ void split_pair_h(float a, float b, __half2* hi, __half2* lo) {
    __half h0 = __float2half_rn(a);
    __half h1 = __float2half_rn(b);
    __half l0 = __float2half_rn(a - __half2float(h0));
    __half l1 = __float2half_rn(b - __half2float(h1));
    *hi = __half2(h0, h1);
    *lo = __half2(l0, l1);
}
__device__ __forceinline__ void h8_to_f8(uint4 raw, float4* a, float4* b) {
    __half2* hp = (__half2*)&raw;
    float2 f0 = __half22float2(hp[0]);
    float2 f1 = __half22float2(hp[1]);
    float2 f2 = __half22float2(hp[2]);
    float2 f3 = __half22float2(hp[3]);
    *a = make_float4(f0.x, f0.y, f1.x, f1.y);
    *b = make_float4(f2.x, f2.y, f3.x, f3.y);
}

/* ==================== LayerNorm + fp16 2-block split ==================== */
__global__ void __launch_bounds__(256) ln_kernel(const float* __restrict__ x,
                                                 const float* __restrict__ gamma,
                                                 const float* __restrict__ beta)
{
    int row  = blockIdx.x * 8 + (threadIdx.x >> 5);
    int lane = threadIdx.x & 31;
    const float* xr = x + (size_t)row * MD;

    float4 a = *(const float4*)(xr + lane * 4);
    float4 b = *(const float4*)(xr + 128 + lane * 4);

    float s  = a.x + a.y + a.z + a.w + b.x + b.y + b.z + b.w;
    float ss = a.x*a.x + a.y*a.y + a.z*a.z + a.w*a.w
             + b.x*b.x + b.y*b.y + b.z*b.z + b.w*b.w;
#pragma unroll
    for (int o = 16; o > 0; o >>= 1) {
        s  += __shfl_xor_sync(0xffffffffu, s,  o);
        ss += __shfl_xor_sync(0xffffffffu, ss, o);
    }
    float mu   = s  * (1.0f / 256.0f);
    float var  = ss * (1.0f / 256.0f) - mu * mu;
    float rstd = rsqrtf(var + 1e-5f);

    float4 g0 = *(const float4*)(gamma + lane * 4);
    float4 g1 = *(const float4*)(gamma + 128 + lane * 4);
    float4 b0 = *(const float4*)(beta  + lane * 4);
    float4 b1 = *(const float4*)(beta  + 128 + lane * 4);

    float r00 = (a.x - mu) * rstd * g0.x + b0.x;
    float r01 = (a.y - mu) * rstd * g0.y + b0.y;
    float r02 = (a.z - mu) * rstd * g0.z + b0.z;
    float r03 = (a.w - mu) * rstd * g0.w + b0.w;
    float r10 = (b.x - mu) * rstd * g1.x + b1.x;
    float r11 = (b.y - mu) * rstd * g1.y + b1.y;
    float r12 = (b.z - mu) * rstd * g1.z + b1.z;
    float r13 = (b.w - mu) * rstd * g1.w + b1.w;

    __half* orow = g_a2 + (size_t)row * K2;
    __half2 h, l;
#define PUT(c, hh, ll) do { \
        *(__half2*)(orow + (c))       = (hh); \
        *(__half2*)(orow + 256 + (c)) = (ll); } while (0)
    split_pair_h(r00, r01, &h, &l);  PUT(lane*4,           h, l);
    split_pair_h(r02, r03, &h, &l);  PUT(lane*4 + 2,       h, l);
    split_pair_h(r10, r11, &h, &l);  PUT(128 + lane*4,     h, l);
    split_pair_h(r12, r13, &h, &l);  PUT(128 + lane*4 + 2, h, l);
#undef PUT
}

/* ==================== weight: [wh | wh] (hi duplicated) ==================== */
__global__ void __launch_bounds__(256) wconv_kernel(const float* __restrict__ Wqkv,
                                                    const float* __restrict__ Wout)
{
    int i = blockIdx.x * 256 + threadIdx.x;   /* grid covers QKVD*MD */
    int n = i >> 8, k = i & 255;
    {
        __half hi = __float2half_rn(Wqkv[i]);
        g_w2qkv[(size_t)n * K2 + k]       = hi;
        g_w2qkv[(size_t)n * K2 + 256 + k] = hi;
    }
    if (i < MD * MD) {
        __half hi = __float2half_rn(Wout[i]);
        g_w2out[(size_t)n * K2 + k]       = hi;
        g_w2out[(size_t)n * K2 + 256 + k] = hi;
    }
}

/* ==================== mma.sync GEMM: C[M,N] = A2[M,512] * W2[N,512]^T ========
   Block tile 128x128, BK=32, 8 warps (warp tile 32x64), cp.async double buffer.
   QKV=true epilogue: cols <512 -> fp16 g_qk16, cols >=512 -> fp32 g_v. */
#define BK      32
#define PITCH   80                  /* 32 fp16 = 64B data, padded to 80B */
#define ASTG    (128 * PITCH)       /* 10240 */
#define STG     (2 * ASTG)          /* 20480 per stage (A+B) */
#define ROWB    (K2 * 2)            /* 1024 B gmem row stride */
#define KIT     (K2 / BK)           /* 16 iterations */

template <bool QKV>
__device__ __forceinline__ void mma_gemm_body(const __half* __restrict__ A2,
                                              const __half* __restrict__ W2,
                                              float* __restrict__ C, int N)
{
    __shared__ __align__(16) char sm[2 * STG];   /* 40 KB */
    uint32_t sbase = smem_u32(sm);

    int tid  = threadIdx.x;
    int wid  = tid >> 5;
    int lane = tid & 31;
    int mBase = blockIdx.x * 128, nBase = blockIdx.y * 128;
    int wm = (wid & 3) * 32;        /* warp row offset */
    int wn = (wid >> 2) * 64;       /* warp col offset */

    const char* Abase = (const char*)(A2 + (size_t)mBase * K2);
    const char* Bbase = (const char*)(W2 + (size_t)nBase * K2);

    int r0 = tid >> 2;              /* 0..63 */
    int cc = (tid & 3) * 16;        /* 0,16,32,48 */

#define LOAD_STAGE(sidx, k0)  do {                                                     \
        uint32_t sb_ = sbase + (sidx) * STG;                                           \
        size_t ko_ = (size_t)(k0) * 2;                                                 \
        CP16(sb_ + r0 * PITCH + cc,               Abase + (size_t)r0 * ROWB + ko_ + cc); \
        CP16(sb_ + (r0 + 64) * PITCH + cc,        Abase + (size_t)(r0 + 64) * ROWB + ko_ + cc); \
        CP16(sb_ + ASTG + r0 * PITCH + cc,        Bbase + (size_t)r0 * ROWB + ko_ + cc); \
        CP16(sb_ + ASTG + (r0 + 64) * PITCH + cc, Bbase + (size_t)(r0 + 64) * ROWB + ko_ + cc); \
        CP_COMMIT();                                                                   \
    } while (0)

    float acc[2][8][4];
#pragma unroll
    for (int mi = 0; mi < 2; mi++)
#pragma unroll
        for (int ni = 0; ni < 8; ni++)
#pragma unroll
            for (int j = 0; j < 4; j++) acc[mi][ni][j] = 0.0f;

    LOAD_STAGE(0, 0);

    for (int it = 0; it < KIT; it++) {
        if (it < KIT - 1) { LOAD_STAGE((it + 1) & 1, (it + 1) * BK); CP_WAIT(1); }
        else              { CP_WAIT(0); }
        __syncthreads();

        uint32_t sb = sbase + (it & 1) * STG;
#pragma unroll
        for (int kk = 0; kk < 2; kk++) {
            uint32_t a[2][4], b[8][2];
#pragma unroll
            for (int mi = 0; mi < 2; mi++) {
                uint32_t addr = sb + (uint32_t)(wm + mi * 16 + (lane & 15)) * PITCH
                              + (uint32_t)((lane >> 4) * 8 + kk * 16) * 2;
                ldmx4(a[mi][0], a[mi][1], a[mi][2], a[mi][3], addr);
            }
#pragma unroll
            for (int ni = 0; ni < 8; ni++) {
                uint32_t addr = sb + ASTG
                              + (uint32_t)(wn + ni * 8 + (lane & 7)) * PITCH
                              + (uint32_t)(((lane >> 3) & 1) * 8 + kk * 16) * 2;
                ldmx2(b[ni][0], b[ni][1], addr);
            }
#pragma unroll
            for (int mi = 0; mi < 2; mi++)
#pragma unroll
                for (int ni = 0; ni < 8; ni++)
                    mma16816(acc[mi][ni], a[mi], b[ni]);
        }
        __syncthreads();
    }

    /* epilogue */
    int trow = lane >> 2, tcol = (lane & 3) * 2;
#pragma unroll
    for (int mi = 0; mi < 2; mi++) {
#pragma unroll
        for (int ni = 0; ni < 8; ni++) {
            int n   = nBase + wn + ni * 8 + tcol;
            int row = mBase + wm + mi * 16 + trow;
            if (QKV) {
                if (n < 512) {   /* q|k -> fp16 */
                    *(__half2*)(g_qk16 + (size_t)row * 512 + n) =
                        __floats2half2_rn(acc[mi][ni][0], acc[mi][ni][1]);
                    *(__half2*)(g_qk16 + (size_t)(row + 8) * 512 + n) =
                        __floats2half2_rn(acc[mi][ni][2], acc[mi][ni][3]);
                } else {         /* v -> fp32 */
                    int nv = n - 512;
                    *(float2*)(g_v + (size_t)row * MD + nv) =
                        make_float2(acc[mi][ni][0], acc[mi][ni][1]);
                    *(float2*)(g_v + (size_t)(row + 8) * MD + nv) =
                        make_float2(acc[mi][ni][2], acc[mi][ni][3]);
                }
            } else {
                float* cp0 = C + (size_t)row * N + n;
                cp0[0] = acc[mi][ni][0];
                cp0[1] = acc[mi][ni][1];
                float* cp1 = cp0 + 8 * (size_t)N;
                cp1[0] = acc[mi][ni][2];
                cp1[1] = acc[mi][ni][3];
            }
        }
    }
#undef LOAD_STAGE
}

__global__ void __launch_bounds__(256) gemm_qkv_mma()
{
    mma_gemm_body<true>(g_a2, g_w2qkv, (float*)0, QKVD);
}
__global__ void __launch_bounds__(256) gemm_out_mma(float* __restrict__ C)
{
    mma_gemm_body<false>(g_att2, g_w2out, C, MD);
}

/* ==================== rotary ==================== */
__device__ __forceinline__ float4 rope4(float4 v, float tlx, float tly, int c)
{
    int p0 = c >> 1;
    float base0 = (p0     < 8) ? tlx : tly;
    float base1 = (p0 + 1 < 8) ? tlx : tly;
    float th0 = base0 * c_invf[p0 & 7];
    float th1 = base1 * c_invf[(p0 + 1) & 7];
    float s0, c0, s1, c1;
    sincosf(th0, &s0, &c0);
    sincosf(th1, &s1, &c1);
    float4 r;
    r.x = v.x * c0 - v.y * s0;
    r.y = v.y * c0 + v.x * s0;
    r.z = v.z * c1 - v.w * s1;
    r.w = v.w * c1 + v.z * s1;
    return r;
}

/* ==================== attention: one block per (b,x,h), 64 thr, 2 q rows ==== */
__global__ void __launch_bounds__(64) attn_kernel(const int* __restrict__ mask)
{
    int blk = blockIdx.x;
    int h   = blk & 7;
    int bx  = blk >> 3;
    int x   = bx & 127;
    int t   = threadIdx.x;          /* 0..63 */

    __shared__ float Ks[128][32];
    __shared__ float Vs[128][32];
    __shared__ float mflag[128];

    float tlx = -1.0f + x * (2.0f / 127.0f);

    /* K tile: fp16 -> fp32 smem (+rope for head 0) */
    {
        const __half* kb = g_qk16 + (size_t)bx * S * 512 + 256 + h * HD;
        int kc  = (t & 3) * 8;       /* 0,8,16,24 */
        int ky0 = t >> 2;            /* 0..15 */
#pragma unroll
        for (int i = 0; i < 8; i++) {
            int y = ky0 + i * 16;
            uint4 raw = *(const uint4*)(kb + (size_t)y * 512 + kc);
            float4 v0, v1;
            h8_to_f8(raw, &v0, &v1);
            if (h == 0) {
                float tly = -1.0f + y * (2.0f / 127.0f);
                v0 = rope4(v0, tlx, tly, kc);
                v1 = rope4(v1, tlx, tly, kc + 4);
            }
            *(float4*)(&Ks[y][kc])     = v0;
            *(float4*)(&Ks[y][kc + 4]) = v1;
        }
    }
    /* V tile: fp32 */
    {
        const float* vb = g_v + (size_t)bx * S * MD + h * HD;
        int vc  = (t & 7) * 4;
        int vy0 = t >> 3;            /* 0..7 */
#pragma unroll
        for (int i = 0; i < 16; i++) {
            int y = vy0 + i * 8;
            *(float4*)(&Vs[y][vc]) = *(const float4*)(vb + (size_t)y * MD + vc);
        }
    }
    mflag[t]      = (mask[bx * S + t]      != 0) ? 1.0f : 0.0f;
    mflag[t + 64] = (mask[bx * S + t + 64] != 0) ? 1.0f : 0.0f;

    /* q rows 2t, 2t+1 (fp16 -> fp32 + rope) */
    float4 q0[8], q1[8];
    {
        const __half* qb = g_qk16 + (size_t)bx * S * 512 + h * HD;
#pragma unroll
        for (int rr = 0; rr < 2; rr++) {
            int r = 2 * t + rr;
            float tly = -1.0f + r * (2.0f / 127.0f);
            float4* qq = rr ? q1 : q0;
#pragma unroll
            for (int i = 0; i < 4; i++) {
                uint4 raw = *(const uint4*)(qb + (size_t)r * 512 + i * 8);
                float4 a, b;
                h8_to_f8(raw, &a, &b);
                if (h == 0) {
                    a = rope4(a, tlx, tly, i * 8);
                    b = rope4(b, tlx, tly, i * 8 + 4);
                }
                qq[2 * i]     = a;
                qq[2 * i + 1] = b;
            }
        }
    }
    __syncthreads();

    float m0 = -INFINITY, l0 = 0.0f, m1 = -INFINITY, l1 = 0.0f;
    float4 o0[8], o1[8];
#pragma unroll
    for (int i = 0; i < 8; i++) {
        o0[i] = make_float4(0.f, 0.f, 0.f, 0.f);
        o1[i] = make_float4(0.f, 0.f, 0.f, 0.f);
    }

    for (int c = 0; c < 16; c++) {
        int k0c = c * 8;
        float sc0[8], sc1[8];
#pragma unroll
        for (int j = 0; j < 8; j++) {
            const float4* kr = (const float4*)(&Ks[k0c + j][0]);
            float s0 = 0.0f, s1 = 0.0f;
#pragma unroll
            for (int i = 0; i < 8; i++) {
                float4 k4 = kr[i];
                s0 = fmaf(q0[i].x, k4.x, s0); s0 = fmaf(q0[i].y, k4.y, s0);
                s0 = fmaf(q0[i].z, k4.z, s0); s0 = fmaf(q0[i].w, k4.w, s0);
                s1 = fmaf(q1[i].x, k4.x, s1); s1 = fmaf(q1[i].y, k4.y, s1);
                s1 = fmaf(q1[i].z, k4.z, s1); s1 = fmaf(q1[i].w, k4.w, s1);
            }
            float mf = mflag[k0c + j];
            sc0[j] = (mf != 0.0f) ? MBIAS : s0 * ATT_SCALE;
            sc1[j] = (mf != 0.0f) ? MBIAS : s1 * ATT_SCALE;
        }

        float cm0 = sc0[0], cm1 = sc1[0];
#pragma unroll
        for (int j = 1; j < 8; j++) { cm0 = fmaxf(cm0, sc0[j]); cm1 = fmaxf(cm1, sc1[j]); }
        float mn0 = fmaxf(m0, cm0), mn1 = fmaxf(m1, cm1);
        float corr0 = __expf(m0 - mn0), corr1 = __expf(m1 - mn1);

        float ps0 = 0.0f, ps1 = 0.0f;
#pragma unroll
        for (int j = 0; j < 8; j++) {
            sc0[j] = __expf(sc0[j] - mn0); ps0 += sc0[j];
            sc1[j] = __expf(sc1[j] - mn1); ps1 += sc1[j];
        }
        l0 = l0 * corr0 + ps0;
        l1 = l1 * corr1 + ps1;

#pragma unroll
        for (int i = 0; i < 8; i++) {
            float4 a0 = o0[i], a1 = o1[i];
            a0.x *= corr0; a0.y *= corr0; a0.z *= corr0; a0.w *= corr0;
            a1.x *= corr1; a1.y *= corr1; a1.z *= corr1; a1.w *= corr1;
#pragma unroll
            for (int j = 0; j < 8; j++) {
                float4 v = *(const float4*)(&Vs[k0c + j][i * 4]);
                float p0 = sc0[j], p1 = sc1[j];
                a0.x = fmaf(p0, v.x, a0.x); a0.y = fmaf(p0, v.y, a0.y);
                a0.z = fmaf(p0, v.z, a0.z); a0.w = fmaf(p0, v.w, a0.w);
                a1.x = fmaf(p1, v.x, a1.x); a1.y = fmaf(p1, v.y, a1.y);
                a1.z = fmaf(p1, v.z, a1.z); a1.w = fmaf(p1, v.w, a1.w);
            }
            o0[i] = a0; o1[i] = a1;
        }
        m0 = mn0; m1 = mn1;
    }

    float inv0 = 1.0f / l0, inv1 = 1.0f / l1;
#pragma unroll
    for (int rr = 0; rr < 2; rr++) {
        float inv = rr ? inv1 : inv0;
        float4* ov = rr ? o1 : o0;
        __half* op = g_att2 + ((size_t)bx * S + 2 * t + rr) * K2 + h * HD;
#pragma unroll
        for (int i = 0; i < 8; i++) {
            __half2 hp, lp;
            split_pair_h(ov[i].x * inv, ov[i].y * inv, &hp, &lp);
            *(__half2*)(op + i * 4)       = hp;
            *(__half2*)(op + 256 + i * 4) = lp;
            split_pair_h(ov[i].z * inv, ov[i].w * inv, &hp, &lp);
            *(__half2*)(op + i * 4 + 2)       = hp;
            *(__half2*)(op + 256 + i * 4 + 2) = lp;
        }
    }
}

/* ==================== launch ==================== */
extern "C" void kernel_launch(void* const* d_in, const int* in_sizes, int n_in,
                              void* d_out, int out_size)
{
    const float* pair_act  = (const float*)d_in[0];
    const int*   pair_mask = (const int*)d_in[1];
    const float* gamma     = (const float*)d_in[2];
    const float* beta      = (const float*)d_in[3];
    const float* Wqkv      = (const float*)d_in[4];
    const float* Wout      = (const float*)d_in[5];
    float*       out       = (float*)d_out;

    ln_kernel<<<NPOS / 8, 256>>>(pair_act, gamma, beta);
    wconv_kernel<<<(QKVD * MD) / 256, 256>>>(Wqkv, Wout);

    dim3 g1(NPOS / 128, QKVD / 128);
    gemm_qkv_mma<<<g1, 256>>>();

    attn_kernel<<<BSZ * S * NH, 64>>>(pair_mask);

    dim3 g2(NPOS / 128, MD / 128);
    gemm_out_mma<<<g2, 256>>>(out);
}